// round 1
// baseline (speedup 1.0000x reference)
#include <cuda_runtime.h>
#include <math.h>

// Fused MSE + SSIM loss:
//   out = mean((p-t)^2) + 1 - mean(S)
// S from 11-tap separable gaussian (sigma=1.5, R=5), edge padding,
// C1=(0.01*2)^2, C2=(0.03*2)^2, sample-cov norm = 1.
//
// Kernel 1: init accumulators + compute gaussian weights in double (matches
//           numpy f64 -> f32 cast in the reference).
// Kernel 2: tiled fused SSIM+MSE, one 32x32 tile per block, atomicAdd(double).
// Kernel 3: finalize scalar.

#define RW    5
#define TILE  32
#define HALO  (TILE + 2*RW)   // 42
#define HST   44              // padded stride for raw tiles
#define CST   33              // padded stride for conv intermediates
#define IMG   512

__device__ double g_acc[2];   // [0] = sum(S), [1] = sum((p-t)^2)
__device__ float  g_K[11];

__global__ void init_kernel() {
    g_acc[0] = 0.0;
    g_acc[1] = 0.0;
    double kk[11];
    double s = 0.0;
    #pragma unroll
    for (int i = 0; i < 11; i++) {
        double t = (double)(i - 5) / 1.5;
        kk[i] = exp(-0.5 * t * t);
        s += kk[i];
    }
    #pragma unroll
    for (int i = 0; i < 11; i++) g_K[i] = (float)(kk[i] / s);
}

__global__ __launch_bounds__(256) void ssim_mse_kernel(
    const float* __restrict__ pred, const float* __restrict__ targ)
{
    __shared__ float sp[HALO][HST];
    __shared__ float st[HALO][HST];
    __shared__ float h0[HALO][CST];  // conv_h(x)
    __shared__ float h1[HALO][CST];  // conv_h(y)
    __shared__ float h2[HALO][CST];  // conv_h(x*x)
    __shared__ float h3[HALO][CST];  // conv_h(y*y)
    __shared__ float h4[HALO][CST];  // conv_h(x*y)
    __shared__ float rs[8], rm[8];

    const float C1f = 0.0004f;   // (0.01*2)^2
    const float C2f = 0.0036f;   // (0.03*2)^2

    const int tid = threadIdx.x;
    const int bx = blockIdx.x * TILE;
    const int by = blockIdx.y * TILE;
    const size_t base = (size_t)blockIdx.z * (IMG * IMG);
    const float* __restrict__ P = pred + base;
    const float* __restrict__ T = targ + base;

    float K[11];
    #pragma unroll
    for (int i = 0; i < 11; i++) K[i] = g_K[i];

    // ---- load halo tiles with clamped (edge) indexing ----
    #pragma unroll
    for (int idx = tid; idx < HALO * HALO; idx += 256) {
        int r = idx / HALO;
        int c = idx - r * HALO;
        int gy = min(max(by + r - RW, 0), IMG - 1);
        int gx = min(max(bx + c - RW, 0), IMG - 1);
        sp[r][c] = P[gy * IMG + gx];
        st[r][c] = T[gy * IMG + gx];
    }
    __syncthreads();

    // ---- horizontal pass: 42 rows x 32 cols, 5 fields ----
    for (int idx = tid; idx < HALO * TILE; idx += 256) {
        int r = idx >> 5;
        int c = idx & 31;
        float a0 = 0.f, a1 = 0.f, a2 = 0.f, a3 = 0.f, a4 = 0.f;
        #pragma unroll
        for (int k = 0; k < 11; k++) {
            float w = K[k];
            float p = sp[r][c + k];
            float t = st[r][c + k];
            float wp = w * p;
            float wt = w * t;
            a0 += wp;
            a1 += wt;
            a2 = fmaf(wp, p, a2);
            a3 = fmaf(wt, t, a3);
            a4 = fmaf(wp, t, a4);
        }
        h0[r][c] = a0; h1[r][c] = a1; h2[r][c] = a2; h3[r][c] = a3; h4[r][c] = a4;
    }
    __syncthreads();

    // ---- vertical pass + S map + MSE ----
    const int tx = tid & 31;
    const int ty = tid >> 5;       // 0..7
    float s_sum = 0.f, m_sum = 0.f;
    #pragma unroll
    for (int rr = 0; rr < 4; rr++) {
        int ry = ty + rr * 8;
        float ux = 0.f, uy = 0.f, uxx = 0.f, uyy = 0.f, uxy = 0.f;
        #pragma unroll
        for (int k = 0; k < 11; k++) {
            float w = K[k];
            ux  = fmaf(w, h0[ry + k][tx], ux);
            uy  = fmaf(w, h1[ry + k][tx], uy);
            uxx = fmaf(w, h2[ry + k][tx], uxx);
            uyy = fmaf(w, h3[ry + k][tx], uyy);
            uxy = fmaf(w, h4[ry + k][tx], uxy);
        }
        float vx  = uxx - ux * ux;
        float vy  = uyy - uy * uy;
        float vxy = uxy - ux * uy;
        float num = (2.f * ux * uy + C1f) * (2.f * vxy + C2f);
        float den = (ux * ux + uy * uy + C1f) * (vx + vy + C2f);
        s_sum += num / den;
        float d = sp[ry + RW][tx + RW] - st[ry + RW][tx + RW];
        m_sum = fmaf(d, d, m_sum);
    }

    // ---- block reduction ----
    #pragma unroll
    for (int o = 16; o > 0; o >>= 1) {
        s_sum += __shfl_down_sync(0xFFFFFFFFu, s_sum, o);
        m_sum += __shfl_down_sync(0xFFFFFFFFu, m_sum, o);
    }
    if (tx == 0) { rs[ty] = s_sum; rm[ty] = m_sum; }
    __syncthreads();
    if (tid == 0) {
        float S = 0.f, M = 0.f;
        #pragma unroll
        for (int i = 0; i < 8; i++) { S += rs[i]; M += rm[i]; }
        atomicAdd(&g_acc[0], (double)S);
        atomicAdd(&g_acc[1], (double)M);
    }
}

__global__ void finalize_kernel(float* __restrict__ out, double inv_n) {
    out[0] = (float)(g_acc[1] * inv_n + 1.0 - g_acc[0] * inv_n);
}

extern "C" void kernel_launch(void* const* d_in, const int* in_sizes, int n_in,
                              void* d_out, int out_size)
{
    const float* pred = (const float*)d_in[0];
    const float* targ = (const float*)d_in[1];
    float* out = (float*)d_out;

    const int n_total = in_sizes[0];
    const int channels = n_total / (IMG * IMG);

    init_kernel<<<1, 1>>>();

    dim3 grid(IMG / TILE, IMG / TILE, channels);
    ssim_mse_kernel<<<grid, 256>>>(pred, targ);

    finalize_kernel<<<1, 1>>>(out, 1.0 / (double)n_total);
}

// round 4
// speedup vs baseline: 1.3079x; 1.3079x over previous
#include <cuda_runtime.h>
#include <math.h>

// Fused MSE + SSIM loss:  out = mean((p-t)^2) + 1 - mean(S)
// 11-tap separable gaussian (sigma=1.5, R=5), edge padding,
// C1=(0.01*2)^2=4e-4, C2=(0.03*2)^2=3.6e-3, cov_norm = 1.
//
// Field reduction: convolve {x, y, (x+y)^2, (x-y)^2}:
//   uxx+uyy = (us2+ud2)/2 ,  uxy = (us2-ud2)/4
// Register sliding windows in both conv passes; vector LDS.

#define RW    5
#define TILE  32
#define HALO  (TILE + 2*RW)   // 42
#define HST   44              // raw tile row stride (mult of 4)
#define CST   36              // conv field row stride (mult of 4)
#define IMG   512

__device__ double g_acc[2];   // [0]=sum(S), [1]=sum((p-t)^2); zero-inited, reset by finalize

__global__ __launch_bounds__(256, 4) void ssim_mse_kernel(
    const float* __restrict__ pred, const float* __restrict__ targ)
{
    __shared__ __align__(16) float sp[HALO][HST];
    __shared__ __align__(16) float st[HALO][HST];
    __shared__ __align__(16) float h0[HALO][CST];  // conv_h(x)
    __shared__ __align__(16) float h1[HALO][CST];  // conv_h(y)
    __shared__ __align__(16) float h2[HALO][CST];  // conv_h((x+y)^2)
    __shared__ __align__(16) float h3[HALO][CST];  // conv_h((x-y)^2)
    __shared__ float Ksm[11];
    __shared__ float rs[8], rm[8];

    const float C1f = 0.0004f;
    const float C2f = 0.0036f;

    const int tid = threadIdx.x;
    const int bx = blockIdx.x * TILE;
    const int by = blockIdx.y * TILE;
    const size_t base = (size_t)blockIdx.z * (IMG * IMG);
    const float* __restrict__ P = pred + base;
    const float* __restrict__ T = targ + base;

    // gaussian weights (per block; ~1e-7 vs f64 reference, negligible)
    if (tid < 11) {
        float t = (float)(tid - 5) * (1.0f / 1.5f);
        Ksm[tid] = expf(-0.5f * t * t);
    }

    // ---- load halo tiles with clamped (edge) indexing ----
    #pragma unroll 4
    for (int idx = tid; idx < HALO * HALO; idx += 256) {
        int r = idx / HALO;
        int c = idx - r * HALO;
        int gy = min(max(by + r - RW, 0), IMG - 1);
        int gx = min(max(bx + c - RW, 0), IMG - 1);
        sp[r][c] = P[gy * IMG + gx];
        st[r][c] = T[gy * IMG + gx];
    }
    __syncthreads();

    // normalize weights into registers
    float K[11];
    {
        float ks = 0.f;
        #pragma unroll
        for (int i = 0; i < 11; i++) ks += Ksm[i];
        float inv = __fdividef(1.0f, ks);
        #pragma unroll
        for (int i = 0; i < 11; i++) K[i] = Ksm[i] * inv;
    }

    // ---- horizontal pass: 42 rows x 8 col-groups of 4 outputs ----
    // per unit: 14-wide register window, 4 outputs, 4 fields
    #pragma unroll 1
    for (int u = tid; u < HALO * 8; u += 256) {
        int r  = u >> 3;
        int c0 = (u & 7) * 4;

        float pv[16], tv[16];
        *(float4*)&pv[0]  = *(const float4*)&sp[r][c0];
        *(float4*)&pv[4]  = *(const float4*)&sp[r][c0 + 4];
        *(float4*)&pv[8]  = *(const float4*)&sp[r][c0 + 8];
        *(float2*)&pv[12] = *(const float2*)&sp[r][c0 + 12];
        *(float4*)&tv[0]  = *(const float4*)&st[r][c0];
        *(float4*)&tv[4]  = *(const float4*)&st[r][c0 + 4];
        *(float4*)&tv[8]  = *(const float4*)&st[r][c0 + 8];
        *(float2*)&tv[12] = *(const float2*)&st[r][c0 + 12];

        float a0[4] = {0.f, 0.f, 0.f, 0.f};
        float a1[4] = {0.f, 0.f, 0.f, 0.f};
        float a2[4] = {0.f, 0.f, 0.f, 0.f};
        float a3[4] = {0.f, 0.f, 0.f, 0.f};
        #pragma unroll
        for (int j = 0; j < 14; j++) {
            float p = pv[j], t = tv[j];
            float s = p + t, d = p - t;
            float s2 = s * s, d2 = d * d;
            #pragma unroll
            for (int oc = 0; oc < 4; oc++) {
                int k = j - oc;
                if (k >= 0 && k <= 10) {
                    float w = K[k];
                    a0[oc] = fmaf(w, p,  a0[oc]);
                    a1[oc] = fmaf(w, t,  a1[oc]);
                    a2[oc] = fmaf(w, s2, a2[oc]);
                    a3[oc] = fmaf(w, d2, a3[oc]);
                }
            }
        }
        *(float4*)&h0[r][c0] = make_float4(a0[0], a0[1], a0[2], a0[3]);
        *(float4*)&h1[r][c0] = make_float4(a1[0], a1[1], a1[2], a1[3]);
        *(float4*)&h2[r][c0] = make_float4(a2[0], a2[1], a2[2], a2[3]);
        *(float4*)&h3[r][c0] = make_float4(a3[0], a3[1], a3[2], a3[3]);
    }
    __syncthreads();

    // ---- vertical pass: 32 cols x 8 row-groups of 4 rows ----
    const int tx = tid & 31;
    const int r0 = (tid >> 5) * 4;

    float a[4][4];   // [row][ux,uy,us2,ud2]
    #pragma unroll
    for (int i = 0; i < 4; i++)
        #pragma unroll
        for (int f = 0; f < 4; f++) a[i][f] = 0.f;

    #pragma unroll
    for (int j = 0; j < 14; j++) {
        float f0 = h0[r0 + j][tx];
        float f1 = h1[r0 + j][tx];
        float f2 = h2[r0 + j][tx];
        float f3 = h3[r0 + j][tx];
        #pragma unroll
        for (int orow = 0; orow < 4; orow++) {
            int k = j - orow;
            if (k >= 0 && k <= 10) {
                float w = K[k];
                a[orow][0] = fmaf(w, f0, a[orow][0]);
                a[orow][1] = fmaf(w, f1, a[orow][1]);
                a[orow][2] = fmaf(w, f2, a[orow][2]);
                a[orow][3] = fmaf(w, f3, a[orow][3]);
            }
        }
    }

    float s_sum = 0.f, m_sum = 0.f;
    #pragma unroll
    for (int orow = 0; orow < 4; orow++) {
        float ux  = a[orow][0];
        float uy  = a[orow][1];
        float us2 = a[orow][2];
        float ud2 = a[orow][3];
        float uxy_sum = (us2 + ud2) * 0.5f;          // uxx + uyy
        float vxy = (us2 - ud2) * 0.25f - ux * uy;   // cov(x,y)
        float vs  = uxy_sum - ux * ux - uy * uy;     // vx + vy
        float num = (2.f * ux * uy + C1f) * (2.f * vxy + C2f);
        float den = (ux * ux + uy * uy + C1f) * (vs + C2f);
        s_sum += __fdividef(num, den);
        float dd = sp[r0 + orow + RW][tx + RW] - st[r0 + orow + RW][tx + RW];
        m_sum = fmaf(dd, dd, m_sum);
    }

    // ---- block reduction ----
    #pragma unroll
    for (int o = 16; o > 0; o >>= 1) {
        s_sum += __shfl_down_sync(0xFFFFFFFFu, s_sum, o);
        m_sum += __shfl_down_sync(0xFFFFFFFFu, m_sum, o);
    }
    const int wy = tid >> 5;
    if (tx == 0) { rs[wy] = s_sum; rm[wy] = m_sum; }
    __syncthreads();
    if (tid == 0) {
        float S = 0.f, M = 0.f;
        #pragma unroll
        for (int i = 0; i < 8; i++) { S += rs[i]; M += rm[i]; }
        atomicAdd(&g_acc[0], (double)S);
        atomicAdd(&g_acc[1], (double)M);
    }
}

__global__ void finalize_kernel(float* __restrict__ out, double inv_n) {
    out[0] = (float)(g_acc[1] * inv_n + 1.0 - g_acc[0] * inv_n);
    g_acc[0] = 0.0;   // reset for next replay (deterministic per call)
    g_acc[1] = 0.0;
}

extern "C" void kernel_launch(void* const* d_in, const int* in_sizes, int n_in,
                              void* d_out, int out_size)
{
    const float* pred = (const float*)d_in[0];
    const float* targ = (const float*)d_in[1];
    float* out = (float*)d_out;

    const int n_total = in_sizes[0];
    const int channels = n_total / (IMG * IMG);

    dim3 grid(IMG / TILE, IMG / TILE, channels);
    ssim_mse_kernel<<<grid, 256>>>(pred, targ);

    finalize_kernel<<<1, 1>>>(out, 1.0 / (double)n_total);
}

// round 6
// speedup vs baseline: 1.4634x; 1.1189x over previous
#include <cuda_runtime.h>
#include <math.h>

// Fused MSE + SSIM loss:  out = mean((p-t)^2) + 1 - mean(S)
// 11-tap separable gaussian (sigma=1.5, R=5), edge padding,
// C1=(0.01*2)^2=4e-4, C2=(0.03*2)^2=3.6e-3, cov_norm = 1.
//
// Field reduction: convolve {x, y, (x+y)^2, (x-y)^2}:
//   uxx+uyy = (us2+ud2)/2 ,  uxy = (us2-ud2)/4
// Register sliding windows in both conv passes; vector LDS.
// Gaussian weights are COMPILE-TIME IMMEDIATES so ptxas emits the
// imm-multiplier FFMA form (rt_SMSP=1, 2x throughput of 3-reg FFMA).

#define RW    5
#define TILE  32
#define HALO  (TILE + 2*RW)   // 42
#define HST   44              // raw tile row stride (mult of 4)
#define CST   36              // conv field row stride (mult of 4)
#define IMG   512

// normalized gaussian weights, sigma=1.5, t=-5..5, computed in f64, cast f32
__device__ constexpr float KW[11] = {
    0.00102838f, 0.00759876f, 0.03600076f, 0.10936070f, 0.21300554f,
    0.26601172f,
    0.21300554f, 0.10936070f, 0.03600076f, 0.00759876f, 0.00102838f
};

__device__ double g_acc[2];   // [0]=sum(S), [1]=sum((p-t)^2); zero-inited, reset by finalize

__global__ __launch_bounds__(256, 4) void ssim_mse_kernel(
    const float* __restrict__ pred, const float* __restrict__ targ)
{
    __shared__ __align__(16) float sp[HALO][HST];
    __shared__ __align__(16) float st[HALO][HST];
    __shared__ __align__(16) float h0[HALO][CST];  // conv_h(x)
    __shared__ __align__(16) float h1[HALO][CST];  // conv_h(y)
    __shared__ __align__(16) float h2[HALO][CST];  // conv_h((x+y)^2)
    __shared__ __align__(16) float h3[HALO][CST];  // conv_h((x-y)^2)
    __shared__ float rs[8], rm[8];

    const float C1f = 0.0004f;
    const float C2f = 0.0036f;

    const int tid = threadIdx.x;
    const int bx = blockIdx.x * TILE;
    const int by = blockIdx.y * TILE;
    const size_t base = (size_t)blockIdx.z * (IMG * IMG);
    const float* __restrict__ P = pred + base;
    const float* __restrict__ T = targ + base;

    // ---- load halo tiles with clamped (edge) indexing ----
    #pragma unroll 4
    for (int idx = tid; idx < HALO * HALO; idx += 256) {
        int r = idx / HALO;
        int c = idx - r * HALO;
        int gy = min(max(by + r - RW, 0), IMG - 1);
        int gx = min(max(bx + c - RW, 0), IMG - 1);
        sp[r][c] = P[gy * IMG + gx];
        st[r][c] = T[gy * IMG + gx];
    }
    __syncthreads();

    // ---- horizontal pass: 42 rows x 8 col-groups of 4 outputs ----
    // per unit: 14-wide register window, 4 outputs, 4 fields
    #pragma unroll 1
    for (int u = tid; u < HALO * 8; u += 256) {
        int r  = u >> 3;
        int c0 = (u & 7) * 4;

        float pv[16], tv[16];
        *(float4*)&pv[0]  = *(const float4*)&sp[r][c0];
        *(float4*)&pv[4]  = *(const float4*)&sp[r][c0 + 4];
        *(float4*)&pv[8]  = *(const float4*)&sp[r][c0 + 8];
        *(float2*)&pv[12] = *(const float2*)&sp[r][c0 + 12];
        *(float4*)&tv[0]  = *(const float4*)&st[r][c0];
        *(float4*)&tv[4]  = *(const float4*)&st[r][c0 + 4];
        *(float4*)&tv[8]  = *(const float4*)&st[r][c0 + 8];
        *(float2*)&tv[12] = *(const float2*)&st[r][c0 + 12];

        float a0[4] = {0.f, 0.f, 0.f, 0.f};
        float a1[4] = {0.f, 0.f, 0.f, 0.f};
        float a2[4] = {0.f, 0.f, 0.f, 0.f};
        float a3[4] = {0.f, 0.f, 0.f, 0.f};
        #pragma unroll
        for (int j = 0; j < 14; j++) {
            float p = pv[j], t = tv[j];
            float s = p + t, d = p - t;
            float s2 = s * s, d2 = d * d;
            #pragma unroll
            for (int oc = 0; oc < 4; oc++) {
                int k = j - oc;
                if (k >= 0 && k <= 10) {
                    a0[oc] = fmaf(KW[k], p,  a0[oc]);
                    a1[oc] = fmaf(KW[k], t,  a1[oc]);
                    a2[oc] = fmaf(KW[k], s2, a2[oc]);
                    a3[oc] = fmaf(KW[k], d2, a3[oc]);
                }
            }
        }
        *(float4*)&h0[r][c0] = make_float4(a0[0], a0[1], a0[2], a0[3]);
        *(float4*)&h1[r][c0] = make_float4(a1[0], a1[1], a1[2], a1[3]);
        *(float4*)&h2[r][c0] = make_float4(a2[0], a2[1], a2[2], a2[3]);
        *(float4*)&h3[r][c0] = make_float4(a3[0], a3[1], a3[2], a3[3]);
    }
    __syncthreads();

    // ---- vertical pass: 32 cols x 8 row-groups of 4 rows ----
    const int tx = tid & 31;
    const int r0 = (tid >> 5) * 4;

    float a[4][4];   // [row][ux,uy,us2,ud2]
    #pragma unroll
    for (int i = 0; i < 4; i++)
        #pragma unroll
        for (int f = 0; f < 4; f++) a[i][f] = 0.f;

    #pragma unroll
    for (int j = 0; j < 14; j++) {
        float f0 = h0[r0 + j][tx];
        float f1 = h1[r0 + j][tx];
        float f2 = h2[r0 + j][tx];
        float f3 = h3[r0 + j][tx];
        #pragma unroll
        for (int orow = 0; orow < 4; orow++) {
            int k = j - orow;
            if (k >= 0 && k <= 10) {
                a[orow][0] = fmaf(KW[k], f0, a[orow][0]);
                a[orow][1] = fmaf(KW[k], f1, a[orow][1]);
                a[orow][2] = fmaf(KW[k], f2, a[orow][2]);
                a[orow][3] = fmaf(KW[k], f3, a[orow][3]);
            }
        }
    }

    float s_sum = 0.f, m_sum = 0.f;
    #pragma unroll
    for (int orow = 0; orow < 4; orow++) {
        float ux  = a[orow][0];
        float uy  = a[orow][1];
        float us2 = a[orow][2];
        float ud2 = a[orow][3];
        float uxy_sum = (us2 + ud2) * 0.5f;          // uxx + uyy
        float vxy = (us2 - ud2) * 0.25f - ux * uy;   // cov(x,y)
        float vs  = uxy_sum - ux * ux - uy * uy;     // vx + vy
        float num = (2.f * ux * uy + C1f) * (2.f * vxy + C2f);
        float den = (ux * ux + uy * uy + C1f) * (vs + C2f);
        s_sum += __fdividef(num, den);
        float dd = sp[r0 + orow + RW][tx + RW] - st[r0 + orow + RW][tx + RW];
        m_sum = fmaf(dd, dd, m_sum);
    }

    // ---- block reduction ----
    #pragma unroll
    for (int o = 16; o > 0; o >>= 1) {
        s_sum += __shfl_down_sync(0xFFFFFFFFu, s_sum, o);
        m_sum += __shfl_down_sync(0xFFFFFFFFu, m_sum, o);
    }
    const int wy = tid >> 5;
    if (tx == 0) { rs[wy] = s_sum; rm[wy] = m_sum; }
    __syncthreads();
    if (tid == 0) {
        float S = 0.f, M = 0.f;
        #pragma unroll
        for (int i = 0; i < 8; i++) { S += rs[i]; M += rm[i]; }
        atomicAdd(&g_acc[0], (double)S);
        atomicAdd(&g_acc[1], (double)M);
    }
}

__global__ void finalize_kernel(float* __restrict__ out, double inv_n) {
    out[0] = (float)(g_acc[1] * inv_n + 1.0 - g_acc[0] * inv_n);
    g_acc[0] = 0.0;   // reset for next replay (deterministic per call)
    g_acc[1] = 0.0;
}

extern "C" void kernel_launch(void* const* d_in, const int* in_sizes, int n_in,
                              void* d_out, int out_size)
{
    const float* pred = (const float*)d_in[0];
    const float* targ = (const float*)d_in[1];
    float* out = (float*)d_out;

    const int n_total = in_sizes[0];
    const int channels = n_total / (IMG * IMG);

    dim3 grid(IMG / TILE, IMG / TILE, channels);
    ssim_mse_kernel<<<grid, 256>>>(pred, targ);

    finalize_kernel<<<1, 1>>>(out, 1.0 / (double)n_total);
}

// round 9
// speedup vs baseline: 1.5715x; 1.0739x over previous
#include <cuda_runtime.h>
#include <math.h>

// Fused MSE + SSIM loss:  out = mean((p-t)^2) + 1 - mean(S)
// 11-tap separable gaussian (sigma=1.5, R=5), edge padding.
// Packed f32x2 (Blackwell) everywhere: pred/target interleaved as (p,t),
// conv fields interleaved as (ux,uy) and (us2,ud2).
//   uxx+uyy = (us2+ud2)/2 ,  uxy = (us2-ud2)/4

#define RW    5
#define TILE  32
#define HALO  (TILE + 2*RW)   // 42
#define HST2  46              // spt row stride in float2 (368B, 16B-aligned)
#define CST2  36              // h-field row stride in float2 (288B)
#define IMG   512

// normalized gaussian weights, sigma=1.5, t=-5..5 (f64-computed, cast f32)
#define KW0 0.00102838f
#define KW1 0.00759876f
#define KW2 0.03600076f
#define KW3 0.10936070f
#define KW4 0.21300554f
#define KW5 0.26601172f

__device__ double g_acc[2];   // [0]=sum(S), [1]=sum((p-t)^2)

typedef unsigned long long u64;

// ---- f32x2 helpers (u64 carrier, "l" constraint) ----
__device__ __forceinline__ u64 pack2(float lo, float hi) {
    u64 d;
    asm("mov.b64 %0, {%1, %2};" : "=l"(d) : "f"(lo), "f"(hi));
    return d;
}
__device__ __forceinline__ void unpack2(u64 v, float& lo, float& hi) {
    asm("mov.b64 {%0, %1}, %2;" : "=f"(lo), "=f"(hi) : "l"(v));
}
__device__ __forceinline__ void fma2(u64& acc, u64 a, u64 b) {
    asm("fma.rn.f32x2 %0, %1, %2, %0;" : "+l"(acc) : "l"(a), "l"(b));
}
__device__ __forceinline__ u64 mul2(u64 a, u64 b) {
    u64 r;
    asm("mul.rn.f32x2 %0, %1, %2;" : "=l"(r) : "l"(a), "l"(b));
    return r;
}

__global__ __launch_bounds__(256, 3) void ssim_mse_kernel(
    const float* __restrict__ pred, const float* __restrict__ targ)
{
    __shared__ __align__(16) float2 spt[HALO][HST2];   // (p, t)
    __shared__ __align__(16) float2 hA[HALO][CST2];    // (conv_h x, conv_h y)
    __shared__ __align__(16) float2 hB[HALO][CST2];    // (conv_h s2, conv_h d2)
    __shared__ float rs[8], rm[8];

    const float C1f = 0.0004f;
    const float C2f = 0.0036f;

    const int tid = threadIdx.x;
    const int bx = blockIdx.x * TILE;
    const int by = blockIdx.y * TILE;
    const size_t base = (size_t)blockIdx.z * (IMG * IMG);
    const float* __restrict__ P = pred + base;
    const float* __restrict__ T = targ + base;

    // weight pairs (w,w); kernel symmetric -> 6 distinct
    u64 wp[6];
    wp[0] = pack2(KW0, KW0); wp[1] = pack2(KW1, KW1); wp[2] = pack2(KW2, KW2);
    wp[3] = pack2(KW3, KW3); wp[4] = pack2(KW4, KW4); wp[5] = pack2(KW5, KW5);

    // ---- load halo, interleaved (p,t), clamped edge indexing ----
    #pragma unroll 4
    for (int idx = tid; idx < HALO * HALO; idx += 256) {
        int r = idx / HALO;
        int c = idx - r * HALO;
        int gy = min(max(by + r - RW, 0), IMG - 1);
        int gx = min(max(bx + c - RW, 0), IMG - 1);
        int g = gy * IMG + gx;
        spt[r][c] = make_float2(P[g], T[g]);
    }
    __syncthreads();

    // ---- horizontal pass: 42 rows x 8 groups of 4 outputs ----
    #pragma unroll 1
    for (int u = tid; u < HALO * 8; u += 256) {
        int r  = u >> 3;
        int c0 = (u & 7) * 4;

        u64 ptw[14];
        #pragma unroll
        for (int i = 0; i < 7; i++) {
            ulonglong2 v = *(const ulonglong2*)&spt[r][c0 + 2 * i];
            ptw[2 * i] = v.x; ptw[2 * i + 1] = v.y;
        }

        u64 a01[4], a23[4];
        #pragma unroll
        for (int oc = 0; oc < 4; oc++) { a01[oc] = 0ULL; a23[oc] = 0ULL; }

        #pragma unroll
        for (int j = 0; j < 14; j++) {
            float p, t;
            unpack2(ptw[j], p, t);
            float s = p + t, d = p - t;
            u64 sd = pack2(s, d);
            u64 s2d2 = mul2(sd, sd);
            #pragma unroll
            for (int oc = 0; oc < 4; oc++) {
                int k = j - oc;
                if (k >= 0 && k <= 10) {
                    int kk = (k <= 5) ? k : 10 - k;
                    fma2(a01[oc], wp[kk], ptw[j]);
                    fma2(a23[oc], wp[kk], s2d2);
                }
            }
        }
        *(ulonglong2*)&hA[r][c0]     = make_ulonglong2(a01[0], a01[1]);
        *(ulonglong2*)&hA[r][c0 + 2] = make_ulonglong2(a01[2], a01[3]);
        *(ulonglong2*)&hB[r][c0]     = make_ulonglong2(a23[0], a23[1]);
        *(ulonglong2*)&hB[r][c0 + 2] = make_ulonglong2(a23[2], a23[3]);
    }
    __syncthreads();

    // ---- vertical pass: 32 cols x 8 groups of 4 rows ----
    const int tx = tid & 31;
    const int r0 = (tid >> 5) * 4;

    u64 aA[4], aB[4];
    #pragma unroll
    for (int i = 0; i < 4; i++) { aA[i] = 0ULL; aB[i] = 0ULL; }

    #pragma unroll
    for (int j = 0; j < 14; j++) {
        u64 fA = *(const u64*)&hA[r0 + j][tx];
        u64 fB = *(const u64*)&hB[r0 + j][tx];
        #pragma unroll
        for (int orow = 0; orow < 4; orow++) {
            int k = j - orow;
            if (k >= 0 && k <= 10) {
                int kk = (k <= 5) ? k : 10 - k;
                fma2(aA[orow], wp[kk], fA);
                fma2(aB[orow], wp[kk], fB);
            }
        }
    }

    float s_sum = 0.f, m_sum = 0.f;
    #pragma unroll
    for (int orow = 0; orow < 4; orow++) {
        float ux, uy, us2, ud2;
        unpack2(aA[orow], ux, uy);
        unpack2(aB[orow], us2, ud2);
        float uxy_sum = (us2 + ud2) * 0.5f;          // uxx + uyy
        float vxy = (us2 - ud2) * 0.25f - ux * uy;   // cov(x,y)
        float vs  = uxy_sum - ux * ux - uy * uy;     // vx + vy
        float num = (2.f * ux * uy + C1f) * (2.f * vxy + C2f);
        float den = (ux * ux + uy * uy + C1f) * (vs + C2f);
        s_sum += __fdividef(num, den);
        float2 pt = spt[r0 + orow + RW][tx + RW];
        float dd = pt.x - pt.y;
        m_sum = fmaf(dd, dd, m_sum);
    }

    // ---- block reduction ----
    #pragma unroll
    for (int o = 16; o > 0; o >>= 1) {
        s_sum += __shfl_down_sync(0xFFFFFFFFu, s_sum, o);
        m_sum += __shfl_down_sync(0xFFFFFFFFu, m_sum, o);
    }
    const int wy = tid >> 5;
    if (tx == 0) { rs[wy] = s_sum; rm[wy] = m_sum; }
    __syncthreads();
    if (tid == 0) {
        float S = 0.f, M = 0.f;
        #pragma unroll
        for (int i = 0; i < 8; i++) { S += rs[i]; M += rm[i]; }
        atomicAdd(&g_acc[0], (double)S);
        atomicAdd(&g_acc[1], (double)M);
    }
}

__global__ void finalize_kernel(float* __restrict__ out, double inv_n) {
    out[0] = (float)(g_acc[1] * inv_n + 1.0 - g_acc[0] * inv_n);
    g_acc[0] = 0.0;   // reset for next graph replay
    g_acc[1] = 0.0;
}

extern "C" void kernel_launch(void* const* d_in, const int* in_sizes, int n_in,
                              void* d_out, int out_size)
{
    const float* pred = (const float*)d_in[0];
    const float* targ = (const float*)d_in[1];
    float* out = (float*)d_out;

    const int n_total = in_sizes[0];
    const int channels = n_total / (IMG * IMG);

    dim3 grid(IMG / TILE, IMG / TILE, channels);
    ssim_mse_kernel<<<grid, 256>>>(pred, targ);

    finalize_kernel<<<1, 1>>>(out, 1.0 / (double)n_total);
}

// round 10
// speedup vs baseline: 1.6715x; 1.0636x over previous
#include <cuda_runtime.h>
#include <math.h>

// Fused MSE + SSIM loss:  out = mean((p-t)^2) + 1 - mean(S)
// 11-tap separable gaussian (sigma=1.5, R=5), edge padding.
// Packed f32x2 (Blackwell): (p,t) / (ux,uy) / (us2,ud2) pairs.
//   uxx+uyy = (us2+ud2)/2 ,  uxy = (us2-ud2)/4
// Single kernel: 32x64 tiles, dynamic smem, last-block finalize.

#define RW    5
#define TW    32              // tile width
#define TH    64              // tile height
#define HW    (TW + 2*RW)     // 42
#define HH    (TH + 2*RW)     // 74
#define HST2  46              // spt row stride in float2 (368B = 16*23)
#define CST2  36              // h-field row stride in float2 (288B = 16*18)
#define IMG   512

#define SPT_BYTES (HH * HST2 * 8)             // 27232
#define HA_BYTES  (HH * CST2 * 8)             // 21312
#define SMEM_BYTES (SPT_BYTES + 2 * HA_BYTES) // 69856

// normalized gaussian weights, sigma=1.5, t=-5..5 (f64-computed, cast f32)
#define KW0 0.00102838f
#define KW1 0.00759876f
#define KW2 0.03600076f
#define KW3 0.10936070f
#define KW4 0.21300554f
#define KW5 0.26601172f

__device__ double g_acc[2];        // [0]=sum(S), [1]=sum((p-t)^2)
__device__ unsigned int g_count;   // blocks-done counter

typedef unsigned long long u64;

// ---- f32x2 helpers (u64 carrier, "l" constraint) ----
__device__ __forceinline__ u64 pack2(float lo, float hi) {
    u64 d;
    asm("mov.b64 %0, {%1, %2};" : "=l"(d) : "f"(lo), "f"(hi));
    return d;
}
__device__ __forceinline__ void unpack2(u64 v, float& lo, float& hi) {
    asm("mov.b64 {%0, %1}, %2;" : "=f"(lo), "=f"(hi) : "l"(v));
}
__device__ __forceinline__ void fma2(u64& acc, u64 a, u64 b) {
    asm("fma.rn.f32x2 %0, %1, %2, %0;" : "+l"(acc) : "l"(a), "l"(b));
}
__device__ __forceinline__ u64 mul2(u64 a, u64 b) {
    u64 r;
    asm("mul.rn.f32x2 %0, %1, %2;" : "=l"(r) : "l"(a), "l"(b));
    return r;
}

__global__ __launch_bounds__(256, 2) void ssim_mse_kernel(
    const float* __restrict__ pred, const float* __restrict__ targ,
    float* __restrict__ out, double inv_n, unsigned int total_blocks)
{
    extern __shared__ __align__(16) char smem_raw[];
    float2 (*spt)[HST2] = (float2(*)[HST2])smem_raw;                        // (p, t)
    float2 (*hA)[CST2]  = (float2(*)[CST2])(smem_raw + SPT_BYTES);          // (hx, hy)
    float2 (*hB)[CST2]  = (float2(*)[CST2])(smem_raw + SPT_BYTES + HA_BYTES); // (hs2, hd2)
    __shared__ float rs[8], rm[8];

    const float C1f = 0.0004f;
    const float C2f = 0.0036f;

    const int tid = threadIdx.x;
    const int bx = blockIdx.x * TW;
    const int by = blockIdx.y * TH;
    const size_t base = (size_t)blockIdx.z * (IMG * IMG);
    const float* __restrict__ P = pred + base;
    const float* __restrict__ T = targ + base;

    // weight pairs (w,w); kernel symmetric -> 6 distinct
    u64 wp[6];
    wp[0] = pack2(KW0, KW0); wp[1] = pack2(KW1, KW1); wp[2] = pack2(KW2, KW2);
    wp[3] = pack2(KW3, KW3); wp[4] = pack2(KW4, KW4); wp[5] = pack2(KW5, KW5);

    // ---- load halo, interleaved (p,t), clamped edge indexing ----
    #pragma unroll 4
    for (int idx = tid; idx < HH * HW; idx += 256) {
        int r = idx / HW;
        int c = idx - r * HW;
        int gy = min(max(by + r - RW, 0), IMG - 1);
        int gx = min(max(bx + c - RW, 0), IMG - 1);
        int g = gy * IMG + gx;
        spt[r][c] = make_float2(P[g], T[g]);
    }
    __syncthreads();

    // ---- horizontal pass: 74 rows x 8 groups of 4 outputs ----
    #pragma unroll 1
    for (int u = tid; u < HH * 8; u += 256) {
        int r  = u >> 3;
        int c0 = (u & 7) * 4;

        u64 ptw[14];
        #pragma unroll
        for (int i = 0; i < 7; i++) {
            ulonglong2 v = *(const ulonglong2*)&spt[r][c0 + 2 * i];
            ptw[2 * i] = v.x; ptw[2 * i + 1] = v.y;
        }

        u64 a01[4], a23[4];
        #pragma unroll
        for (int oc = 0; oc < 4; oc++) { a01[oc] = 0ULL; a23[oc] = 0ULL; }

        #pragma unroll
        for (int j = 0; j < 14; j++) {
            float p, t;
            unpack2(ptw[j], p, t);
            float s = p + t, d = p - t;
            u64 sd = pack2(s, d);
            u64 s2d2 = mul2(sd, sd);
            #pragma unroll
            for (int oc = 0; oc < 4; oc++) {
                int k = j - oc;
                if (k >= 0 && k <= 10) {
                    int kk = (k <= 5) ? k : 10 - k;
                    fma2(a01[oc], wp[kk], ptw[j]);
                    fma2(a23[oc], wp[kk], s2d2);
                }
            }
        }
        *(ulonglong2*)&hA[r][c0]     = make_ulonglong2(a01[0], a01[1]);
        *(ulonglong2*)&hA[r][c0 + 2] = make_ulonglong2(a01[2], a01[3]);
        *(ulonglong2*)&hB[r][c0]     = make_ulonglong2(a23[0], a23[1]);
        *(ulonglong2*)&hB[r][c0 + 2] = make_ulonglong2(a23[2], a23[3]);
    }
    __syncthreads();

    // ---- vertical pass: 2 passes of 32 rows (8 warps x 4 rows) ----
    const int tx = tid & 31;
    float s_sum = 0.f, m_sum = 0.f;

    #pragma unroll
    for (int rr = 0; rr < 2; rr++) {
        const int r0 = (tid >> 5) * 4 + rr * 32;

        u64 aA[4], aB[4];
        #pragma unroll
        for (int i = 0; i < 4; i++) { aA[i] = 0ULL; aB[i] = 0ULL; }

        #pragma unroll
        for (int j = 0; j < 14; j++) {
            u64 fA = *(const u64*)&hA[r0 + j][tx];
            u64 fB = *(const u64*)&hB[r0 + j][tx];
            #pragma unroll
            for (int orow = 0; orow < 4; orow++) {
                int k = j - orow;
                if (k >= 0 && k <= 10) {
                    int kk = (k <= 5) ? k : 10 - k;
                    fma2(aA[orow], wp[kk], fA);
                    fma2(aB[orow], wp[kk], fB);
                }
            }
        }

        #pragma unroll
        for (int orow = 0; orow < 4; orow++) {
            float ux, uy, us2, ud2;
            unpack2(aA[orow], ux, uy);
            unpack2(aB[orow], us2, ud2);
            float uxy_sum = (us2 + ud2) * 0.5f;          // uxx + uyy
            float vxy = (us2 - ud2) * 0.25f - ux * uy;   // cov(x,y)
            float vs  = uxy_sum - ux * ux - uy * uy;     // vx + vy
            float num = (2.f * ux * uy + C1f) * (2.f * vxy + C2f);
            float den = (ux * ux + uy * uy + C1f) * (vs + C2f);
            s_sum += __fdividef(num, den);
            float2 pt = spt[r0 + orow + RW][tx + RW];
            float dd = pt.x - pt.y;
            m_sum = fmaf(dd, dd, m_sum);
        }
    }

    // ---- block reduction ----
    #pragma unroll
    for (int o = 16; o > 0; o >>= 1) {
        s_sum += __shfl_down_sync(0xFFFFFFFFu, s_sum, o);
        m_sum += __shfl_down_sync(0xFFFFFFFFu, m_sum, o);
    }
    const int wy = tid >> 5;
    if (tx == 0) { rs[wy] = s_sum; rm[wy] = m_sum; }
    __syncthreads();

    if (tid == 0) {
        float S = 0.f, M = 0.f;
        #pragma unroll
        for (int i = 0; i < 8; i++) { S += rs[i]; M += rm[i]; }
        atomicAdd(&g_acc[0], (double)S);
        atomicAdd(&g_acc[1], (double)M);
        __threadfence();
        unsigned int done = atomicAdd(&g_count, 1u);
        if (done == total_blocks - 1u) {
            // last block: finalize + reset for next graph replay
            double Sg = g_acc[0];
            double Mg = g_acc[1];
            out[0] = (float)(Mg * inv_n + 1.0 - Sg * inv_n);
            g_acc[0] = 0.0;
            g_acc[1] = 0.0;
            g_count = 0u;
            __threadfence();
        }
    }
}

extern "C" void kernel_launch(void* const* d_in, const int* in_sizes, int n_in,
                              void* d_out, int out_size)
{
    const float* pred = (const float*)d_in[0];
    const float* targ = (const float*)d_in[1];
    float* out = (float*)d_out;

    const int n_total = in_sizes[0];
    const int channels = n_total / (IMG * IMG);

    static int attr_set = 0;
    if (!attr_set) {
        cudaFuncSetAttribute(ssim_mse_kernel,
                             cudaFuncAttributeMaxDynamicSharedMemorySize,
                             SMEM_BYTES);
        attr_set = 1;
    }

    dim3 grid(IMG / TW, IMG / TH, channels);
    unsigned int total_blocks = grid.x * grid.y * grid.z;
    ssim_mse_kernel<<<grid, 256, SMEM_BYTES>>>(pred, targ, out,
                                               1.0 / (double)n_total,
                                               total_blocks);
}

// round 13
// speedup vs baseline: 1.7707x; 1.0593x over previous
#include <cuda_runtime.h>
#include <math.h>

// Fused MSE + SSIM loss:  out = mean((p-t)^2) + 1 - mean(S)
// 11-tap separable gaussian (sigma=1.5, R=5), edge padding.
// Packed f32x2: (p,t) pairs; h-fields interleaved per point as
// ulonglong2{ (hx,hy), (hs2,hd2) } -> one LDS.128 per vertical tap.
//   uxx+uyy = (us2+ud2)/2 ,  uxy = (us2-ud2)/4
// 32x64 tiles, 8-out horizontal windows, 8-row vertical groups,
// MSE folded into load phase, last-block finalize. 3 blocks/SM.

#define RW    5
#define TW    32              // tile width
#define TH    64              // tile height
#define HW    (TW + 2*RW)     // 42
#define HH    (TH + 2*RW)     // 74
#define HST2  46              // spt row stride in float2 (368B, 92 words % 32 = 28)
#define CSTE  33              // hAB row stride in ulonglong2 (528B, 132 words % 32 = 4)
#define IMG   512

#define SPT_BYTES  (HH * HST2 * 8)              // 27232
#define HAB_BYTES  (HH * CSTE * 16)             // 39072
#define SMEM_BYTES (SPT_BYTES + HAB_BYTES)      // 66304

// normalized gaussian weights, sigma=1.5, t=-5..5 (f64-computed, cast f32)
#define KW0 0.00102838f
#define KW1 0.00759876f
#define KW2 0.03600076f
#define KW3 0.10936070f
#define KW4 0.21300554f
#define KW5 0.26601172f

__device__ double g_acc[2];        // [0]=sum(S), [1]=sum((p-t)^2)
__device__ unsigned int g_count;   // blocks-done counter

typedef unsigned long long u64;

// ---- f32x2 helpers (u64 carrier, "l" constraint) ----
__device__ __forceinline__ u64 pack2(float lo, float hi) {
    u64 d;
    asm("mov.b64 %0, {%1, %2};" : "=l"(d) : "f"(lo), "f"(hi));
    return d;
}
__device__ __forceinline__ void unpack2(u64 v, float& lo, float& hi) {
    asm("mov.b64 {%0, %1}, %2;" : "=f"(lo), "=f"(hi) : "l"(v));
}
__device__ __forceinline__ void fma2(u64& acc, u64 a, u64 b) {
    asm("fma.rn.f32x2 %0, %1, %2, %0;" : "+l"(acc) : "l"(a), "l"(b));
}
__device__ __forceinline__ u64 mul2(u64 a, u64 b) {
    u64 r;
    asm("mul.rn.f32x2 %0, %1, %2;" : "=l"(r) : "l"(a), "l"(b));
    return r;
}

__global__ __launch_bounds__(256, 3) void ssim_mse_kernel(
    const float* __restrict__ pred, const float* __restrict__ targ,
    float* __restrict__ out, double inv_n, unsigned int total_blocks)
{
    extern __shared__ __align__(16) char smem_raw[];
    float2     (*spt)[HST2] = (float2(*)[HST2])smem_raw;              // (p, t)
    ulonglong2 (*hAB)[CSTE] = (ulonglong2(*)[CSTE])(smem_raw + SPT_BYTES); // {(hx,hy),(hs2,hd2)}
    __shared__ float rs[8], rm[8];

    const float C1f = 0.0004f;
    const float C2f = 0.0036f;

    const int tid = threadIdx.x;
    const int bx = blockIdx.x * TW;
    const int by = blockIdx.y * TH;
    const size_t base = (size_t)blockIdx.z * (IMG * IMG);
    const float* __restrict__ P = pred + base;
    const float* __restrict__ T = targ + base;

    // weight pairs (w,w); kernel symmetric -> 6 distinct
    u64 wp[6];
    wp[0] = pack2(KW0, KW0); wp[1] = pack2(KW1, KW1); wp[2] = pack2(KW2, KW2);
    wp[3] = pack2(KW3, KW3); wp[4] = pack2(KW4, KW4); wp[5] = pack2(KW5, KW5);

    float m_sum = 0.f;

    // ---- load halo (p,t) with edge clamping; MSE on interior pixels ----
    #pragma unroll 4
    for (int idx = tid; idx < HH * HW; idx += 256) {
        int r = idx / HW;
        int c = idx - r * HW;
        int gy = min(max(by + r - RW, 0), IMG - 1);
        int gx = min(max(bx + c - RW, 0), IMG - 1);
        int g = gy * IMG + gx;
        float p = P[g], t = T[g];
        spt[r][c] = make_float2(p, t);
        if (r >= RW && r < RW + TH && c >= RW && c < RW + TW) {
            float dd = p - t;
            m_sum = fmaf(dd, dd, m_sum);
        }
    }
    __syncthreads();

    // ---- horizontal pass: HH rows x 4 groups of 8 outputs ----
    // unit u: row = u % HH, cg = u / HH  (warp = 32 consecutive rows, same cg)
    #pragma unroll 1
    for (int u = tid; u < HH * 4; u += 256) {
        int row = u % HH;
        int cg  = u / HH;
        int c0  = cg * 8;

        u64 a01[8], a23[8];
        #pragma unroll
        for (int oc = 0; oc < 8; oc++) { a01[oc] = 0ULL; a23[oc] = 0ULL; }

        #pragma unroll
        for (int i = 0; i < 9; i++) {
            ulonglong2 v = *(const ulonglong2*)&spt[row][c0 + 2 * i];
            #pragma unroll
            for (int half = 0; half < 2; half++) {
                int j = 2 * i + half;
                u64 pt = half ? v.y : v.x;
                float p, t;
                unpack2(pt, p, t);
                float s = p + t, d = p - t;
                u64 s2d2 = mul2(pack2(s, d), pack2(s, d));
                #pragma unroll
                for (int oc = 0; oc < 8; oc++) {
                    int k = j - oc;
                    if (k >= 0 && k <= 10) {
                        int kk = (k <= 5) ? k : 10 - k;
                        fma2(a01[oc], wp[kk], pt);
                        fma2(a23[oc], wp[kk], s2d2);
                    }
                }
            }
        }
        #pragma unroll
        for (int oc = 0; oc < 8; oc++)
            hAB[row][c0 + oc] = make_ulonglong2(a01[oc], a23[oc]);
    }
    __syncthreads();

    // ---- vertical pass: 32 cols x 8 groups of 8 rows ----
    const int tx = tid & 31;
    const int r0 = (tid >> 5) * 8;

    u64 aA[8], aB[8];
    #pragma unroll
    for (int i = 0; i < 8; i++) { aA[i] = 0ULL; aB[i] = 0ULL; }

    #pragma unroll
    for (int j = 0; j < 18; j++) {
        ulonglong2 f = hAB[r0 + j][tx];
        #pragma unroll
        for (int orow = 0; orow < 8; orow++) {
            int k = j - orow;
            if (k >= 0 && k <= 10) {
                int kk = (k <= 5) ? k : 10 - k;
                fma2(aA[orow], wp[kk], f.x);
                fma2(aB[orow], wp[kk], f.y);
            }
        }
    }

    float s_sum = 0.f;
    #pragma unroll
    for (int orow = 0; orow < 8; orow++) {
        float ux, uy, us2, ud2;
        unpack2(aA[orow], ux, uy);
        unpack2(aB[orow], us2, ud2);
        float uxy_sum = (us2 + ud2) * 0.5f;          // uxx + uyy
        float vxy = (us2 - ud2) * 0.25f - ux * uy;   // cov(x,y)
        float vs  = uxy_sum - ux * ux - uy * uy;     // vx + vy
        float num = (2.f * ux * uy + C1f) * (2.f * vxy + C2f);
        float den = (ux * ux + uy * uy + C1f) * (vs + C2f);
        s_sum += __fdividef(num, den);
    }

    // ---- block reduction ----
    #pragma unroll
    for (int o = 16; o > 0; o >>= 1) {
        s_sum += __shfl_down_sync(0xFFFFFFFFu, s_sum, o);
        m_sum += __shfl_down_sync(0xFFFFFFFFu, m_sum, o);
    }
    const int wy = tid >> 5;
    if (tx == 0) { rs[wy] = s_sum; rm[wy] = m_sum; }
    __syncthreads();

    if (tid == 0) {
        float S = 0.f, M = 0.f;
        #pragma unroll
        for (int i = 0; i < 8; i++) { S += rs[i]; M += rm[i]; }
        atomicAdd(&g_acc[0], (double)S);
        atomicAdd(&g_acc[1], (double)M);
        __threadfence();
        unsigned int done = atomicAdd(&g_count, 1u);
        if (done == total_blocks - 1u) {
            // last block: finalize + reset for next graph replay
            double Sg = g_acc[0];
            double Mg = g_acc[1];
            out[0] = (float)(Mg * inv_n + 1.0 - Sg * inv_n);
            g_acc[0] = 0.0;
            g_acc[1] = 0.0;
            g_count = 0u;
            __threadfence();
        }
    }
}

extern "C" void kernel_launch(void* const* d_in, const int* in_sizes, int n_in,
                              void* d_out, int out_size)
{
    const float* pred = (const float*)d_in[0];
    const float* targ = (const float*)d_in[1];
    float* out = (float*)d_out;

    const int n_total = in_sizes[0];
    const int channels = n_total / (IMG * IMG);

    static int attr_set = 0;
    if (!attr_set) {
        cudaFuncSetAttribute(ssim_mse_kernel,
                             cudaFuncAttributeMaxDynamicSharedMemorySize,
                             SMEM_BYTES);
        attr_set = 1;
    }

    dim3 grid(IMG / TW, IMG / TH, channels);
    unsigned int total_blocks = grid.x * grid.y * grid.z;
    ssim_mse_kernel<<<grid, 256, SMEM_BYTES>>>(pred, targ, out,
                                               1.0 / (double)n_total,
                                               total_blocks);
}